// round 12
// baseline (speedup 1.0000x reference)
#include <cuda_runtime.h>

#define NTHREADS 256
#define TB 8
#define EDIM 1024
#define NQ 8

typedef unsigned long long u64;

__device__ __forceinline__ u64 pack2(float lo, float hi) {
    u64 r; asm("mov.b64 %0, {%1, %2};" : "=l"(r) : "f"(lo), "f"(hi)); return r;
}
__device__ __forceinline__ u64 packdup(float v) {
    u64 r; asm("mov.b64 %0, {%1, %1};" : "=l"(r) : "f"(v)); return r;
}
__device__ __forceinline__ void unpack2(u64 p, float& lo, float& hi) {
    asm("mov.b64 {%0, %1}, %2;" : "=f"(lo), "=f"(hi) : "l"(p));
}
__device__ __forceinline__ u64 mul2(u64 a, u64 b) {
    u64 r; asm("mul.rn.f32x2 %0, %1, %2;" : "=l"(r) : "l"(a), "l"(b)); return r;
}
__device__ __forceinline__ u64 fma2(u64 a, u64 b, u64 c) {
    u64 r; asm("fma.rn.f32x2 %0, %1, %2, %3;" : "=l"(r) : "l"(a), "l"(b), "l"(c)); return r;
}
__device__ __forceinline__ u64 add2(u64 a, u64 b) {
    u64 r; asm("add.rn.f32x2 %0, %1, %2;" : "=l"(r) : "l"(a), "l"(b)); return r;
}

// non-hoistable 128-bit global load (keeps W_out out of persistent registers)
#define LDG128(v, p) asm volatile("ld.global.nc.v4.f32 {%0,%1,%2,%3}, [%4];" \
    : "=f"((v).x), "=f"((v).y), "=f"((v).z), "=f"((v).w) : "l"(p))

// psum: 4 qubit-pair class arrays, each [TB][256] u64 = 16 KB -> 64 KB total
#define PS_CLASS 16384u
#define ZD_OFF   65536u                 // zdup: TB*16 floats = 512 B
#define CTH_OFF  (ZD_OFF + 512u)
#define BI_OFF   (CTH_OFF + 32u)
#define SMEM_BYTES (BI_OFF + 32u)       // 66,112 B -> 3 CTAs/SM (198 KB)

__global__ __launch_bounds__(NTHREADS, 3)
void qff_fused(const float* __restrict__ x,
               const float* __restrict__ W_in,
               const float* __restrict__ b_in,
               const float* __restrict__ theta,
               const float* __restrict__ W_out,
               const float* __restrict__ b_out,
               float* __restrict__ out,
               int n_tokens)
{
    extern __shared__ char smc[];
    float* zdup = reinterpret_cast<float*>(smc + ZD_OFF);
    float* cth  = reinterpret_cast<float*>(smc + CTH_OFF);
    float* bi   = reinterpret_cast<float*>(smc + BI_OFF);

    const int tid  = threadIdx.x;
    const int lane = tid & 31;
    const int wrp  = tid >> 5;

    if (tid < NQ) { cth[tid] = cosf(theta[tid]); bi[tid] = b_in[tid]; }

    // W_in pairs resident: wi[pr][c] = (W_in[2pr][4t+c], W_in[2pr+1][4t+c])
    u64 wi[4][4];
#pragma unroll
    for (int pr = 0; pr < 4; pr++) {
        float4 wa = reinterpret_cast<const float4*>(W_in + (2*pr  )*EDIM)[tid];
        float4 wb = reinterpret_cast<const float4*>(W_in + (2*pr+1)*EDIM)[tid];
        wi[pr][0] = pack2(wa.x, wb.x);
        wi[pr][1] = pack2(wa.y, wb.y);
        wi[pr][2] = pack2(wa.z, wb.z);
        wi[pr][3] = pack2(wa.w, wb.w);
    }
    u64 bo01, bo23;
    { float4 bo = reinterpret_cast<const float4*>(b_out)[tid];
      bo01 = pack2(bo.x, bo.y); bo23 = pack2(bo.z, bo.w); }

    // stage-2 lane constants (proven R5 addressing)
    const int pr2 = lane >> 3;
    const int c8  = lane & 7;
    const unsigned ex = ((unsigned)(2*c8 + (pr2 & 1))) << 3;
    const char* s2base = smc + (unsigned)pr2*PS_CLASS
                       + (unsigned)wrp*2048u + (unsigned)c8*256u;

    const int nbatches = n_tokens / TB;          // 4096
    const int stride   = gridDim.x;
    const float4* x4 = reinterpret_cast<const float4*>(x);

    for (int b = blockIdx.x; b < nbatches; b += stride) {
        // ---- phase 1: two waves of 4 tokens (caps xv live range at 16 regs) ----
#pragma unroll
        for (int h = 0; h < 2; h++) {
            float4 xv[4];
            const float4* xr = x4 + ((long)b*TB + h*4)*(EDIM/4) + tid;
#pragma unroll
            for (int t = 0; t < 4; t++) xv[t] = xr[t*(EDIM/4)];
#pragma unroll
            for (int t = 0; t < 4; t++) {
                const int tt = h*4 + t;
                u64 xx = packdup(xv[t].x), xy = packdup(xv[t].y);
                u64 xz = packdup(xv[t].z), xw = packdup(xv[t].w);
#pragma unroll
                for (int pr = 0; pr < 4; pr++) {
                    u64 p = mul2(xx, wi[pr][0]);
                    p = fma2(xy, wi[pr][1], p);
                    p = fma2(xz, wi[pr][2], p);
                    p = fma2(xw, wi[pr][3], p);
                    *reinterpret_cast<u64*>(smc + (unsigned)pr*PS_CLASS
                        + ((unsigned)tt*256u + (unsigned)tid)*8u) = p;
                }
            }
        }
        __syncthreads();   // psum ready (+ cth/bi first iter)

        // ---- stage 2: warp wrp reduces token wrp ----
        {
            u64 a0 = *reinterpret_cast<const u64*>(s2base + (( 0u<<3) ^ ex));
            u64 a1 = *reinterpret_cast<const u64*>(s2base + (( 1u<<3) ^ ex));
            u64 a2 = *reinterpret_cast<const u64*>(s2base + (( 2u<<3) ^ ex));
            u64 a3 = *reinterpret_cast<const u64*>(s2base + (( 3u<<3) ^ ex));
#pragma unroll
            for (int j = 4; j < 32; j += 4) {
                a0 = add2(a0, *reinterpret_cast<const u64*>(s2base + (((unsigned)(j+0)<<3) ^ ex)));
                a1 = add2(a1, *reinterpret_cast<const u64*>(s2base + (((unsigned)(j+1)<<3) ^ ex)));
                a2 = add2(a2, *reinterpret_cast<const u64*>(s2base + (((unsigned)(j+2)<<3) ^ ex)));
                a3 = add2(a3, *reinterpret_cast<const u64*>(s2base + (((unsigned)(j+3)<<3) ^ ex)));
            }
            u64 acc = add2(add2(a0, a1), add2(a2, a3));
            acc = add2(acc, __shfl_down_sync(0xffffffffu, acc, 4, 8));
            acc = add2(acc, __shfl_down_sync(0xffffffffu, acc, 2, 8));
            acc = add2(acc, __shfl_down_sync(0xffffffffu, acc, 1, 8));
            float sa, sb2; unpack2(acc, sa, sb2);
            float ma = cth[2*pr2  ] * cosf(sa  + bi[2*pr2  ]);
            float mb = cth[2*pr2+1] * cosf(sb2 + bi[2*pr2+1]);
            float pp = ma * mb;
            float incl = pp, tt;
            tt = __shfl_up_sync(0xffffffffu, incl, 8);  if (lane >= 8)  incl *= tt;
            tt = __shfl_up_sync(0xffffffffu, incl, 16); if (lane >= 16) incl *= tt;
            float E = __shfl_up_sync(0xffffffffu, incl, 8);
            if (pr2 == 0) E = 1.0f;
            float za = E * ma, zb = E * pp;
            if (c8 == 0)
                reinterpret_cast<float4*>(zdup + wrp*16)[pr2] = make_float4(za, za, zb, zb);
        }
        __syncthreads();   // zdup ready; psum free for next batch

        // ---- phase 3: two passes, W_out reloaded per pass (16 regs live) ----
        float* obase = out + (long)b*TB*EDIM + 4*tid;
#pragma unroll
        for (int half = 0; half < 2; half++) {
            const float* wrow = W_out + (4*tid + 2*half)*NQ;   // rows e, e+1
            float4 aLo, aHi, bLo, bHi;
            LDG128(aLo, wrow);      LDG128(aHi, wrow + 4);
            LDG128(bLo, wrow + 8);  LDG128(bHi, wrow + 12);
            u64 w0 = pack2(aLo.x, bLo.x), w1 = pack2(aLo.y, bLo.y);
            u64 w2 = pack2(aLo.z, bLo.z), w3 = pack2(aLo.w, bLo.w);
            u64 w4 = pack2(aHi.x, bHi.x), w5 = pack2(aHi.y, bHi.y);
            u64 w6 = pack2(aHi.z, bHi.z), w7 = pack2(aHi.w, bHi.w);
            const u64 bo = half ? bo23 : bo01;
#pragma unroll
            for (int t = 0; t < TB; t++) {
                const ulonglong2* zr = reinterpret_cast<const ulonglong2*>(zdup + t*16);
                ulonglong2 zA = zr[0], zB = zr[1];
                u64 acc = bo;
                acc = fma2(zA.x, w0, acc); acc = fma2(zA.y, w1, acc);
                acc = fma2(zB.x, w2, acc); acc = fma2(zB.y, w3, acc);
                ulonglong2 zC = zr[2], zD = zr[3];
                acc = fma2(zC.x, w4, acc); acc = fma2(zC.y, w5, acc);
                acc = fma2(zD.x, w6, acc); acc = fma2(zD.y, w7, acc);
                float a0f, a1f; unpack2(acc, a0f, a1f);
                *reinterpret_cast<float2*>(obase + t*EDIM + 2*half)
                    = make_float2(fmaxf(a0f, 0.f), fmaxf(a1f, 0.f));
            }
        }
        // no trailing barrier: next phase1 touches only psum (disjoint from zdup);
        // next stage2's zdup writes are fenced by the next post-phase1 sync.
    }
}

extern "C" void kernel_launch(void* const* d_in, const int* in_sizes, int n_in,
                              void* d_out, int out_size) {
    const float* x     = (const float*)d_in[0];
    const float* W_in  = (const float*)d_in[1];
    const float* b_in  = (const float*)d_in[2];
    const float* theta = (const float*)d_in[3];
    const float* W_out = (const float*)d_in[4];
    const float* b_out = (const float*)d_in[5];
    float* out = (float*)d_out;

    const int n_tokens = in_sizes[0] / EDIM;   // 32768

    cudaFuncSetAttribute(qff_fused, cudaFuncAttributeMaxDynamicSharedMemorySize,
                         (int)SMEM_BYTES);
    qff_fused<<<444, NTHREADS, SMEM_BYTES>>>(x, W_in, b_in, theta, W_out, b_out,
                                             out, n_tokens);
}

// round 13
// speedup vs baseline: 1.1472x; 1.1472x over previous
#include <cuda_runtime.h>

#define NTHREADS 256
#define TB 8
#define EDIM 1024
#define NQ 8

typedef unsigned long long u64;

__device__ __forceinline__ u64 pack2(float lo, float hi) {
    u64 r; asm("mov.b64 %0, {%1, %2};" : "=l"(r) : "f"(lo), "f"(hi)); return r;
}
__device__ __forceinline__ u64 packdup(float v) {
    u64 r; asm("mov.b64 %0, {%1, %1};" : "=l"(r) : "f"(v)); return r;
}
__device__ __forceinline__ void unpack2(u64 p, float& lo, float& hi) {
    asm("mov.b64 {%0, %1}, %2;" : "=f"(lo), "=f"(hi) : "l"(p));
}
__device__ __forceinline__ u64 mul2(u64 a, u64 b) {
    u64 r; asm("mul.rn.f32x2 %0, %1, %2;" : "=l"(r) : "l"(a), "l"(b)); return r;
}
__device__ __forceinline__ u64 fma2(u64 a, u64 b, u64 c) {
    u64 r; asm("fma.rn.f32x2 %0, %1, %2, %3;" : "=l"(r) : "l"(a), "l"(b), "l"(c)); return r;
}
__device__ __forceinline__ u64 add2(u64 a, u64 b) {
    u64 r; asm("add.rn.f32x2 %0, %1, %2;" : "=l"(r) : "l"(a), "l"(b)); return r;
}

// non-hoistable 128-bit global load (keeps W_out out of persistent registers)
#define LDG128(v, p) asm volatile("ld.global.nc.v4.f32 {%0,%1,%2,%3}, [%4];" \
    : "=f"((v).x), "=f"((v).y), "=f"((v).z), "=f"((v).w) : "l"(p))

// psum: 4 qubit-pair class arrays, each [TB][256] u64 = 16 KB -> 64 KB total
#define PS_CLASS 16384u
#define ZD_OFF   65536u                 // zdup: TB*16 floats = 512 B
#define CTH_OFF  (ZD_OFF + 512u)
#define BI_OFF   (CTH_OFF + 32u)
#define SMEM_BYTES (BI_OFF + 32u)       // 66,112 B -> 3 CTAs/SM (198 KB)

__global__ __launch_bounds__(NTHREADS, 3)
void qff_fused(const float* __restrict__ x,
               const float* __restrict__ W_in,
               const float* __restrict__ b_in,
               const float* __restrict__ theta,
               const float* __restrict__ W_out,
               const float* __restrict__ b_out,
               float* __restrict__ out,
               int n_tokens)
{
    extern __shared__ char smc[];
    float* zdup = reinterpret_cast<float*>(smc + ZD_OFF);
    float* cth  = reinterpret_cast<float*>(smc + CTH_OFF);
    float* bi   = reinterpret_cast<float*>(smc + BI_OFF);

    const int tid  = threadIdx.x;
    const int lane = tid & 31;
    const int wrp  = tid >> 5;

    if (tid < NQ) { cth[tid] = cosf(theta[tid]); bi[tid] = b_in[tid]; }

    // W_in pairs resident: wi[pr][c] = (W_in[2pr][4t+c], W_in[2pr+1][4t+c])
    u64 wi[4][4];
#pragma unroll
    for (int pr = 0; pr < 4; pr++) {
        float4 wa = reinterpret_cast<const float4*>(W_in + (2*pr  )*EDIM)[tid];
        float4 wb = reinterpret_cast<const float4*>(W_in + (2*pr+1)*EDIM)[tid];
        wi[pr][0] = pack2(wa.x, wb.x);
        wi[pr][1] = pack2(wa.y, wb.y);
        wi[pr][2] = pack2(wa.z, wb.z);
        wi[pr][3] = pack2(wa.w, wb.w);
    }
    // bias for the two phase-3 column pairs: (2t, 2t+1) and (512+2t, 512+2t+1)
    u64 boA, boB;
    {
        float2 bA = reinterpret_cast<const float2*>(b_out)[tid];
        float2 bB = reinterpret_cast<const float2*>(b_out + 512)[tid];
        boA = pack2(bA.x, bA.y);
        boB = pack2(bB.x, bB.y);
    }

    // stage-2 lane constants (proven R5 addressing)
    const int pr2 = lane >> 3;
    const int c8  = lane & 7;
    const unsigned ex = ((unsigned)(2*c8 + (pr2 & 1))) << 3;
    const char* s2base = smc + (unsigned)pr2*PS_CLASS
                       + (unsigned)wrp*2048u + (unsigned)c8*256u;

    const int nbatches = n_tokens / TB;          // 4096
    const int stride   = gridDim.x;
    const float4* x4 = reinterpret_cast<const float4*>(x);

    for (int b = blockIdx.x; b < nbatches; b += stride) {
        // ---- phase 1: two waves of 4 tokens (caps xv live range at 16 regs) ----
#pragma unroll
        for (int h = 0; h < 2; h++) {
            float4 xv[4];
            const float4* xr = x4 + ((long)b*TB + h*4)*(EDIM/4) + tid;
#pragma unroll
            for (int t = 0; t < 4; t++) xv[t] = xr[t*(EDIM/4)];
#pragma unroll
            for (int t = 0; t < 4; t++) {
                const int tt = h*4 + t;
                u64 xx = packdup(xv[t].x), xy = packdup(xv[t].y);
                u64 xz = packdup(xv[t].z), xw = packdup(xv[t].w);
#pragma unroll
                for (int pr = 0; pr < 4; pr++) {
                    u64 p = mul2(xx, wi[pr][0]);
                    p = fma2(xy, wi[pr][1], p);
                    p = fma2(xz, wi[pr][2], p);
                    p = fma2(xw, wi[pr][3], p);
                    *reinterpret_cast<u64*>(smc + (unsigned)pr*PS_CLASS
                        + ((unsigned)tt*256u + (unsigned)tid)*8u) = p;
                }
            }
        }
        __syncthreads();   // psum ready (+ cth/bi first iter)

        // ---- stage 2: warp wrp reduces token wrp ----
        {
            u64 a0 = *reinterpret_cast<const u64*>(s2base + (( 0u<<3) ^ ex));
            u64 a1 = *reinterpret_cast<const u64*>(s2base + (( 1u<<3) ^ ex));
            u64 a2 = *reinterpret_cast<const u64*>(s2base + (( 2u<<3) ^ ex));
            u64 a3 = *reinterpret_cast<const u64*>(s2base + (( 3u<<3) ^ ex));
#pragma unroll
            for (int j = 4; j < 32; j += 4) {
                a0 = add2(a0, *reinterpret_cast<const u64*>(s2base + (((unsigned)(j+0)<<3) ^ ex)));
                a1 = add2(a1, *reinterpret_cast<const u64*>(s2base + (((unsigned)(j+1)<<3) ^ ex)));
                a2 = add2(a2, *reinterpret_cast<const u64*>(s2base + (((unsigned)(j+2)<<3) ^ ex)));
                a3 = add2(a3, *reinterpret_cast<const u64*>(s2base + (((unsigned)(j+3)<<3) ^ ex)));
            }
            u64 acc = add2(add2(a0, a1), add2(a2, a3));
            acc = add2(acc, __shfl_down_sync(0xffffffffu, acc, 4, 8));
            acc = add2(acc, __shfl_down_sync(0xffffffffu, acc, 2, 8));
            acc = add2(acc, __shfl_down_sync(0xffffffffu, acc, 1, 8));
            float sa, sb2; unpack2(acc, sa, sb2);
            float ma = cth[2*pr2  ] * cosf(sa  + bi[2*pr2  ]);
            float mb = cth[2*pr2+1] * cosf(sb2 + bi[2*pr2+1]);
            float pp = ma * mb;
            float incl = pp, tt;
            tt = __shfl_up_sync(0xffffffffu, incl, 8);  if (lane >= 8)  incl *= tt;
            tt = __shfl_up_sync(0xffffffffu, incl, 16); if (lane >= 16) incl *= tt;
            float E = __shfl_up_sync(0xffffffffu, incl, 8);
            if (pr2 == 0) E = 1.0f;
            float za = E * ma, zb = E * pp;
            if (c8 == 0)
                reinterpret_cast<float4*>(zdup + wrp*16)[pr2] = make_float4(za, za, zb, zb);
        }
        __syncthreads();   // zdup ready; psum free for next batch

        // ---- phase 3: two passes over contiguous column halves ----
        // pass `half` -> columns e0 = half*512 + 2*tid, e0+1 (coalesced float2 stores)
        float* obase = out + (long)b*TB*EDIM + 2*tid;
#pragma unroll
        for (int half = 0; half < 2; half++) {
            const float* wrow = W_out + (half*512 + 2*tid)*NQ;   // rows e0, e0+1 (64 B)
            float4 aLo, aHi, bLo, bHi;
            LDG128(aLo, wrow);      LDG128(aHi, wrow + 4);
            LDG128(bLo, wrow + 8);  LDG128(bHi, wrow + 12);
            u64 w0 = pack2(aLo.x, bLo.x), w1 = pack2(aLo.y, bLo.y);
            u64 w2 = pack2(aLo.z, bLo.z), w3 = pack2(aLo.w, bLo.w);
            u64 w4 = pack2(aHi.x, bHi.x), w5 = pack2(aHi.y, bHi.y);
            u64 w6 = pack2(aHi.z, bHi.z), w7 = pack2(aHi.w, bHi.w);
            const u64 bo = half ? boB : boA;
#pragma unroll
            for (int t = 0; t < TB; t++) {
                const ulonglong2* zr = reinterpret_cast<const ulonglong2*>(zdup + t*16);
                ulonglong2 zA = zr[0], zB = zr[1];
                u64 acc = bo;
                acc = fma2(zA.x, w0, acc); acc = fma2(zA.y, w1, acc);
                acc = fma2(zB.x, w2, acc); acc = fma2(zB.y, w3, acc);
                ulonglong2 zC = zr[2], zD = zr[3];
                acc = fma2(zC.x, w4, acc); acc = fma2(zC.y, w5, acc);
                acc = fma2(zD.x, w6, acc); acc = fma2(zD.y, w7, acc);
                float a0f, a1f; unpack2(acc, a0f, a1f);
                *reinterpret_cast<float2*>(obase + t*EDIM + half*512)
                    = make_float2(fmaxf(a0f, 0.f), fmaxf(a1f, 0.f));
            }
        }
        // no trailing barrier: next phase1 touches only psum (disjoint from zdup);
        // next stage2's zdup writes are fenced by the next post-phase1 sync.
    }
}

extern "C" void kernel_launch(void* const* d_in, const int* in_sizes, int n_in,
                              void* d_out, int out_size) {
    const float* x     = (const float*)d_in[0];
    const float* W_in  = (const float*)d_in[1];
    const float* b_in  = (const float*)d_in[2];
    const float* theta = (const float*)d_in[3];
    const float* W_out = (const float*)d_in[4];
    const float* b_out = (const float*)d_in[5];
    float* out = (float*)d_out;

    const int n_tokens = in_sizes[0] / EDIM;   // 32768

    cudaFuncSetAttribute(qff_fused, cudaFuncAttributeMaxDynamicSharedMemorySize,
                         (int)SMEM_BYTES);
    qff_fused<<<444, NTHREADS, SMEM_BYTES>>>(x, W_in, b_in, theta, W_out, b_out,
                                             out, n_tokens);
}

// round 14
// speedup vs baseline: 3.2988x; 2.8756x over previous
#include <cuda_runtime.h>

#define NTHREADS 256
#define TB 8
#define EDIM 1024
#define NQ 8

typedef unsigned long long u64;

__device__ __forceinline__ u64 pack2(float lo, float hi) {
    u64 r; asm("mov.b64 %0, {%1, %2};" : "=l"(r) : "f"(lo), "f"(hi)); return r;
}
__device__ __forceinline__ u64 packdup(float v) {
    u64 r; asm("mov.b64 %0, {%1, %1};" : "=l"(r) : "f"(v)); return r;
}
__device__ __forceinline__ void unpack2(u64 p, float& lo, float& hi) {
    asm("mov.b64 {%0, %1}, %2;" : "=f"(lo), "=f"(hi) : "l"(p));
}
__device__ __forceinline__ u64 mul2(u64 a, u64 b) {
    u64 r; asm("mul.rn.f32x2 %0, %1, %2;" : "=l"(r) : "l"(a), "l"(b)); return r;
}
__device__ __forceinline__ u64 fma2(u64 a, u64 b, u64 c) {
    u64 r; asm("fma.rn.f32x2 %0, %1, %2, %3;" : "=l"(r) : "l"(a), "l"(b), "l"(c)); return r;
}
__device__ __forceinline__ u64 add2(u64 a, u64 b) {
    u64 r; asm("add.rn.f32x2 %0, %1, %2;" : "=l"(r) : "l"(a), "l"(b)); return r;
}

// psum: two ulonglong2 arrays [TB][256]: AB = (q01,q23), CD = (q45,q67). 32 KB each.
#define PSAB_OFF 0u
#define PSCD_OFF 32768u
#define ZD_OFF   65536u                 // zdup: TB*16 floats = 512 B
#define CTH_OFF  (ZD_OFF + 512u)
#define BI_OFF   (CTH_OFF + 32u)
#define SMEM_BYTES (BI_OFF + 32u)       // 66,112 B -> 2 CTAs/SM

__global__ __launch_bounds__(NTHREADS, 2)
void qff_fused(const float* __restrict__ x,
               const float* __restrict__ W_in,
               const float* __restrict__ b_in,
               const float* __restrict__ theta,
               const float* __restrict__ W_out,
               const float* __restrict__ b_out,
               float* __restrict__ out,
               int n_tokens)
{
    extern __shared__ char smc[];
    float* zdup = reinterpret_cast<float*>(smc + ZD_OFF);
    float* cth  = reinterpret_cast<float*>(smc + CTH_OFF);
    float* bi   = reinterpret_cast<float*>(smc + BI_OFF);

    const int tid  = threadIdx.x;
    const int lane = tid & 31;
    const int wrp  = tid >> 5;

    if (tid < NQ) { cth[tid] = cosf(theta[tid]); bi[tid] = b_in[tid]; }

    // W_in pairs resident: wi[pr][c] = (W_in[2pr][4t+c], W_in[2pr+1][4t+c])
    u64 wi[4][4];
#pragma unroll
    for (int pr = 0; pr < 4; pr++) {
        float4 wa = reinterpret_cast<const float4*>(W_in + (2*pr  )*EDIM)[tid];
        float4 wb = reinterpret_cast<const float4*>(W_in + (2*pr+1)*EDIM)[tid];
        wi[pr][0] = pack2(wa.x, wb.x);
        wi[pr][1] = pack2(wa.y, wb.y);
        wi[pr][2] = pack2(wa.z, wb.z);
        wi[pr][3] = pack2(wa.w, wb.w);
    }
    // W_out pairs + bias resident (R5 layout: thread owns cols 4t..4t+3)
    u64 wo01[8], wo23[8], bo01, bo23;
    {
        float4 rA[4], rB[4];
#pragma unroll
        for (int j = 0; j < 4; j++) {
            rA[j] = reinterpret_cast<const float4*>(W_out)[(4*tid+j)*2 + 0];
            rB[j] = reinterpret_cast<const float4*>(W_out)[(4*tid+j)*2 + 1];
        }
        wo01[0]=pack2(rA[0].x,rA[1].x); wo01[1]=pack2(rA[0].y,rA[1].y);
        wo01[2]=pack2(rA[0].z,rA[1].z); wo01[3]=pack2(rA[0].w,rA[1].w);
        wo01[4]=pack2(rB[0].x,rB[1].x); wo01[5]=pack2(rB[0].y,rB[1].y);
        wo01[6]=pack2(rB[0].z,rB[1].z); wo01[7]=pack2(rB[0].w,rB[1].w);
        wo23[0]=pack2(rA[2].x,rA[3].x); wo23[1]=pack2(rA[2].y,rA[3].y);
        wo23[2]=pack2(rA[2].z,rA[3].z); wo23[3]=pack2(rA[2].w,rA[3].w);
        wo23[4]=pack2(rB[2].x,rB[3].x); wo23[5]=pack2(rB[2].y,rB[3].y);
        wo23[6]=pack2(rB[2].z,rB[3].z); wo23[7]=pack2(rB[2].w,rB[3].w);
        float4 bo = reinterpret_cast<const float4*>(b_out)[tid];
        bo01 = pack2(bo.x, bo.y); bo23 = pack2(bo.z, bo.w);
    }

    // stage-2 lane constants (R10-verified layout: entry i at i*16 + 8*(pr2&1))
    const int pr2 = lane >> 3;           // qubit pair
    const int c8  = lane & 7;            // chunk: entries i = c8 + 8j
    const char* s2base = smc + ((pr2 & 2) ? PSCD_OFF : PSAB_OFF)
                       + (unsigned)wrp * 4096u
                       + (unsigned)c8 * 16u
                       + ((pr2 & 1) ? 8u : 0u);

    const int nbatches = n_tokens / TB;          // 4096
    const int stride   = gridDim.x;
    const float4* x4 = reinterpret_cast<const float4*>(x);
    float4* out4 = reinterpret_cast<float4*>(out);

    float4 xv[TB];
    #define LOADX(bb) { const float4* xr_ = x4 + (long)(bb)*TB*(EDIM/4) + tid; \
        _Pragma("unroll") for (int t_ = 0; t_ < TB; t_++) xv[t_] = xr_[t_*(EDIM/4)]; }

    int b = blockIdx.x;
    if (b >= nbatches) return;
    LOADX(b);

    for (; b < nbatches; b += stride) {
        // ---- phase 1: packed partial dots, 2x STS.128 per token ----
#pragma unroll
        for (int t = 0; t < TB; t++) {
            u64 xx = packdup(xv[t].x), xy = packdup(xv[t].y);
            u64 xz = packdup(xv[t].z), xw = packdup(xv[t].w);
            u64 p0 = mul2(xx, wi[0][0]); p0 = fma2(xy, wi[0][1], p0);
            p0 = fma2(xz, wi[0][2], p0); p0 = fma2(xw, wi[0][3], p0);
            u64 p1 = mul2(xx, wi[1][0]); p1 = fma2(xy, wi[1][1], p1);
            p1 = fma2(xz, wi[1][2], p1); p1 = fma2(xw, wi[1][3], p1);
            u64 p2 = mul2(xx, wi[2][0]); p2 = fma2(xy, wi[2][1], p2);
            p2 = fma2(xz, wi[2][2], p2); p2 = fma2(xw, wi[2][3], p2);
            u64 p3 = mul2(xx, wi[3][0]); p3 = fma2(xy, wi[3][1], p3);
            p3 = fma2(xz, wi[3][2], p3); p3 = fma2(xw, wi[3][3], p3);
            reinterpret_cast<ulonglong2*>(smc + PSAB_OFF + (unsigned)t*4096u)[tid]
                = make_ulonglong2(p0, p1);
            reinterpret_cast<ulonglong2*>(smc + PSCD_OFF + (unsigned)t*4096u)[tid]
                = make_ulonglong2(p2, p3);
        }

        // ---- prefetch next batch's x (xv dead) ----
        {
            int nb = b + stride;
            const int pb = (nb < nbatches) ? nb : b;
            LOADX(pb);
        }
        __syncthreads();   // sync A: psum ready (+ cth/bi on first iter)

        // ---- stage 2: warp wrp reduces token wrp ----
        {
            u64 a0 = *reinterpret_cast<const u64*>(s2base + 128u*0);
            u64 a1 = *reinterpret_cast<const u64*>(s2base + 128u*1);
            u64 a2 = *reinterpret_cast<const u64*>(s2base + 128u*2);
            u64 a3 = *reinterpret_cast<const u64*>(s2base + 128u*3);
#pragma unroll
            for (int j = 4; j < 32; j += 4) {
                a0 = add2(a0, *reinterpret_cast<const u64*>(s2base + 128u*(j+0)));
                a1 = add2(a1, *reinterpret_cast<const u64*>(s2base + 128u*(j+1)));
                a2 = add2(a2, *reinterpret_cast<const u64*>(s2base + 128u*(j+2)));
                a3 = add2(a3, *reinterpret_cast<const u64*>(s2base + 128u*(j+3)));
            }
            u64 acc = add2(add2(a0, a1), add2(a2, a3));
            acc = add2(acc, __shfl_down_sync(0xffffffffu, acc, 4, 8));
            acc = add2(acc, __shfl_down_sync(0xffffffffu, acc, 2, 8));
            acc = add2(acc, __shfl_down_sync(0xffffffffu, acc, 1, 8));
            float sa, sb2; unpack2(acc, sa, sb2);
            float ma = cth[2*pr2  ] * __cosf(sa  + bi[2*pr2  ]);
            float mb = cth[2*pr2+1] * __cosf(sb2 + bi[2*pr2+1]);
            float pp = ma * mb;
            float incl = pp, tt;
            tt = __shfl_up_sync(0xffffffffu, incl, 8);  if (lane >= 8)  incl *= tt;
            tt = __shfl_up_sync(0xffffffffu, incl, 16); if (lane >= 16) incl *= tt;
            float E = __shfl_up_sync(0xffffffffu, incl, 8);
            if (pr2 == 0) E = 1.0f;
            float za = E * ma, zb = E * pp;
            if (c8 == 0)
                reinterpret_cast<float4*>(zdup + wrp*16)[pr2] = make_float4(za, za, zb, zb);
        }
        __syncthreads();   // sync B: zdup ready, psum free

        // ---- phase 3: out = relu(z @ W_out^T + b_out) ----
        float4* orow = out4 + (long)b * TB * (EDIM/4) + tid;
#pragma unroll
        for (int t = 0; t < TB; t++) {
            const ulonglong2* zr = reinterpret_cast<const ulonglong2*>(zdup + t*16);
            ulonglong2 z01 = zr[0], z23 = zr[1], z45 = zr[2], z67 = zr[3];
            u64 acc01 = bo01, acc23 = bo23;
            acc01 = fma2(z01.x, wo01[0], acc01);  acc23 = fma2(z01.x, wo23[0], acc23);
            acc01 = fma2(z01.y, wo01[1], acc01);  acc23 = fma2(z01.y, wo23[1], acc23);
            acc01 = fma2(z23.x, wo01[2], acc01);  acc23 = fma2(z23.x, wo23[2], acc23);
            acc01 = fma2(z23.y, wo01[3], acc01);  acc23 = fma2(z23.y, wo23[3], acc23);
            acc01 = fma2(z45.x, wo01[4], acc01);  acc23 = fma2(z45.x, wo23[4], acc23);
            acc01 = fma2(z45.y, wo01[5], acc01);  acc23 = fma2(z45.y, wo23[5], acc23);
            acc01 = fma2(z67.x, wo01[6], acc01);  acc23 = fma2(z67.x, wo23[6], acc23);
            acc01 = fma2(z67.y, wo01[7], acc01);  acc23 = fma2(z67.y, wo23[7], acc23);
            float a0f, a1f, a2f, a3f;
            unpack2(acc01, a0f, a1f); unpack2(acc23, a2f, a3f);
            orow[t*(EDIM/4)] = make_float4(fmaxf(a0f,0.f), fmaxf(a1f,0.f),
                                           fmaxf(a2f,0.f), fmaxf(a3f,0.f));
        }
        // next-iter psum writes guarded by sync B; next zdup writes by next sync A
    }
    #undef LOADX
}

extern "C" void kernel_launch(void* const* d_in, const int* in_sizes, int n_in,
                              void* d_out, int out_size) {
    const float* x     = (const float*)d_in[0];
    const float* W_in  = (const float*)d_in[1];
    const float* b_in  = (const float*)d_in[2];
    const float* theta = (const float*)d_in[3];
    const float* W_out = (const float*)d_in[4];
    const float* b_out = (const float*)d_in[5];
    float* out = (float*)d_out;

    const int n_tokens = in_sizes[0] / EDIM;   // 32768

    cudaFuncSetAttribute(qff_fused, cudaFuncAttributeMaxDynamicSharedMemorySize,
                         (int)SMEM_BYTES);
    qff_fused<<<296, NTHREADS, SMEM_BYTES>>>(x, W_in, b_in, theta, W_out, b_out,
                                             out, n_tokens);
}